// round 5
// baseline (speedup 1.0000x reference)
#include <cuda_runtime.h>
#include <cuda_bf16.h>
#include <cstdint>

// LightGCN propagation: N=100000, E=1600000, D=64, L=3.
// out = (x0 + x1 + x2 + x3)/4, x_{l+1} = A_norm @ x_l (with self loops).
//
// R5: vectorized index ingestion, dinv fused into scan1, broadcast-load edge
// walk (no shfl), out-accumulation deferred entirely to layer 3.

#define NN 100000
#define EE 1600000
#define DD 64
#define ND (NN * DD)       // 6,400,000 floats
#define ND4 (ND / 4)       // 1,600,000 float4
#define NB 391             // ceil(NN / 256)

// Scratch (allocation-free: __device__ globals)
__device__ int g_is32;
__device__ float g_deg[NN];      // source-occurrence degree (incl. self loop)
__device__ float g_dinv[NN];
__device__ int g_indeg[NN];      // destination in-degree (excl. self loop)
__device__ int g_part[NB];
__device__ int g_boff[NB];
__device__ int g_start[NN + 1];  // CSR row starts (by destination)
__device__ int g_cursor[NN];
__device__ uint2 g_csr[EE];      // packed (src, norm_bits), grouped by dst
__device__ float4 g_xA[ND4];
__device__ float4 g_xB[ND4];

// ---------------------------------------------------------------------------
// Init: degrees + index-dtype detection (JAX w/o x64 demotes int64 -> int32;
// element count is identical either way, so sample values to disambiguate).
// ---------------------------------------------------------------------------
__global__ __launch_bounds__(256) void k_init(const void* __restrict__ idx) {
    int i = blockIdx.x * blockDim.x + threadIdx.x;
    if (i < NN) {
        g_deg[i] = 1.0f;   // self loop contributes 1 to every degree
        g_indeg[i] = 0;
    }
    if (i == 0) {
        const long long* p = (const long long*)idx;
        int is64 = 1;
        for (int k = 0; k < 256; k++) {
            long long v = p[k];
            if (v < 0 || v >= (long long)NN) { is64 = 0; break; }
        }
        g_is32 = !is64;
    }
}

// 4 edges per thread, vectorized int4 loads on the int32 path.
__global__ __launch_bounds__(256) void k_count(const void* __restrict__ idx) {
    int t = blockIdx.x * blockDim.x + threadIdx.x;
    int e = t * 4;
    if (e >= EE) return;
    int s0, s1, s2, s3, d0, d1, d2, d3;
    if (g_is32) {
        const int4* p = (const int4*)idx;
        int4 s = __ldg(&p[t]);
        int4 d = __ldg(&p[EE / 4 + t]);
        s0 = s.x; s1 = s.y; s2 = s.z; s3 = s.w;
        d0 = d.x; d1 = d.y; d2 = d.z; d3 = d.w;
    } else {
        const long long* p = (const long long*)idx;
        s0 = (int)p[e];      s1 = (int)p[e + 1];
        s2 = (int)p[e + 2];  s3 = (int)p[e + 3];
        d0 = (int)p[EE + e];     d1 = (int)p[EE + e + 1];
        d2 = (int)p[EE + e + 2]; d3 = (int)p[EE + e + 3];
    }
    atomicAdd(&g_deg[s0], 1.0f); atomicAdd(&g_deg[s1], 1.0f);
    atomicAdd(&g_deg[s2], 1.0f); atomicAdd(&g_deg[s3], 1.0f);
    atomicAdd(&g_indeg[d0], 1);  atomicAdd(&g_indeg[d1], 1);
    atomicAdd(&g_indeg[d2], 1);  atomicAdd(&g_indeg[d3], 1);
}

// ---------------------------------------------------------------------------
// Scan of in-degrees -> CSR starts (3-kernel hierarchy). scan1 also computes
// dinv (both depend only on k_count).
// ---------------------------------------------------------------------------
__global__ __launch_bounds__(256) void k_scan1() {
    __shared__ int sh[256];
    int i = blockIdx.x * 256 + threadIdx.x;
    sh[threadIdx.x] = (i < NN) ? g_indeg[i] : 0;
    if (i < NN) {
        float d = g_deg[i];
        g_dinv[i] = (d > 0.0f) ? rsqrtf(d) : 0.0f;
    }
    __syncthreads();
    for (int s = 128; s > 0; s >>= 1) {
        if (threadIdx.x < s) sh[threadIdx.x] += sh[threadIdx.x + s];
        __syncthreads();
    }
    if (threadIdx.x == 0) g_part[blockIdx.x] = sh[0];
}

__global__ __launch_bounds__(512) void k_scan2() {
    __shared__ int sh[512];
    int t = threadIdx.x;
    sh[t] = (t < NB) ? g_part[t] : 0;
    __syncthreads();
    for (int off = 1; off < 512; off <<= 1) {
        int v = (t >= off) ? sh[t - off] : 0;
        __syncthreads();
        sh[t] += v;
        __syncthreads();
    }
    if (t < NB) g_boff[t] = (t == 0) ? 0 : sh[t - 1];
}

__global__ __launch_bounds__(256) void k_scan3() {
    __shared__ int sh[256];
    int i = blockIdx.x * 256 + threadIdx.x;
    int v = (i < NN) ? g_indeg[i] : 0;
    sh[threadIdx.x] = v;
    __syncthreads();
    for (int off = 1; off < 256; off <<= 1) {
        int t = (threadIdx.x >= off) ? sh[threadIdx.x - off] : 0;
        __syncthreads();
        sh[threadIdx.x] += t;
        __syncthreads();
    }
    if (i < NN) {
        int excl = g_boff[blockIdx.x] + sh[threadIdx.x] - v;
        g_start[i] = excl;
        g_cursor[i] = excl;
        if (i == NN - 1) g_start[NN] = excl + v;
    }
}

// Fill CSR: 2 edges per thread, vectorized loads on the int32 path.
__global__ __launch_bounds__(256) void k_fill(const void* __restrict__ idx,
                                              const float* __restrict__ w) {
    int t = blockIdx.x * blockDim.x + threadIdx.x;
    int e = t * 2;
    if (e >= EE) return;
    int s0, s1, d0, d1;
    if (g_is32) {
        const int2* p = (const int2*)idx;
        int2 s = __ldg(&p[t]);
        int2 d = __ldg(&p[EE / 2 + t]);
        s0 = s.x; s1 = s.y; d0 = d.x; d1 = d.y;
    } else {
        const long long* p = (const long long*)idx;
        s0 = (int)p[e]; s1 = (int)p[e + 1];
        d0 = (int)p[EE + e]; d1 = (int)p[EE + e + 1];
    }
    float2 wv = __ldg((const float2*)(w + e));
    float n0 = g_dinv[s0] * wv.x * g_dinv[d0];
    float n1 = g_dinv[s1] * wv.y * g_dinv[d1];
    int p0 = atomicAdd(&g_cursor[d0], 1);
    g_csr[p0] = make_uint2((unsigned)s0, __float_as_uint(n0));
    int p1 = atomicAdd(&g_cursor[d1], 1);
    g_csr[p1] = make_uint2((unsigned)s1, __float_as_uint(n1));
}

// ---------------------------------------------------------------------------
// Layer kernel: 16-lane group per node, one float4 column per lane.
// Edge records are read via broadcast loads (all 16 lanes, same address -> one
// L1 transaction), unrolled x4 for gather MLP.
//   acc = dinv[n]^2 * xOld[n] + sum_{e in CSR[n]} norm[e] * xOld[src[e]]
// mode 0/1: xNew = acc
// mode 2:   out = (x0 + x1 + xOld + acc) * 0.25   (xOld == x2)
// ---------------------------------------------------------------------------
__global__ __launch_bounds__(256) void k_layer(const float4* __restrict__ xOld,
                                               float4* __restrict__ xNew,
                                               const float4* __restrict__ x0,
                                               const float4* __restrict__ x1,
                                               float4* __restrict__ out,
                                               int mode) {
    int tid = threadIdx.x;
    int lane = tid & 15;
    int node = blockIdx.x * 16 + (tid >> 4);   // grid covers exactly NN

    int start = g_start[node];
    int end = g_start[node + 1];
    float s = g_dinv[node];
    s *= s;

    int o = node * 16 + lane;
    float4 v0 = xOld[o];
    float ax = s * v0.x, ay = s * v0.y, az = s * v0.z, aw = s * v0.w;

    const uint2* cp = g_csr + start;
    int cnt = end - start;
    int e = 0;
    for (; e + 4 <= cnt; e += 4) {
        uint2 e0 = __ldg(cp + e);
        uint2 e1 = __ldg(cp + e + 1);
        uint2 e2 = __ldg(cp + e + 2);
        uint2 e3 = __ldg(cp + e + 3);
        float4 a0 = __ldg(&xOld[e0.x * 16 + lane]);
        float4 a1 = __ldg(&xOld[e1.x * 16 + lane]);
        float4 a2 = __ldg(&xOld[e2.x * 16 + lane]);
        float4 a3 = __ldg(&xOld[e3.x * 16 + lane]);
        float n0 = __uint_as_float(e0.y), n1 = __uint_as_float(e1.y);
        float n2 = __uint_as_float(e2.y), n3 = __uint_as_float(e3.y);
        ax = fmaf(n0, a0.x, ax); ay = fmaf(n0, a0.y, ay);
        az = fmaf(n0, a0.z, az); aw = fmaf(n0, a0.w, aw);
        ax = fmaf(n1, a1.x, ax); ay = fmaf(n1, a1.y, ay);
        az = fmaf(n1, a1.z, az); aw = fmaf(n1, a1.w, aw);
        ax = fmaf(n2, a2.x, ax); ay = fmaf(n2, a2.y, ay);
        az = fmaf(n2, a2.z, az); aw = fmaf(n2, a2.w, aw);
        ax = fmaf(n3, a3.x, ax); ay = fmaf(n3, a3.y, ay);
        az = fmaf(n3, a3.z, az); aw = fmaf(n3, a3.w, aw);
    }
    for (; e < cnt; e++) {
        uint2 ed = __ldg(cp + e);
        float nf = __uint_as_float(ed.y);
        float4 v = __ldg(&xOld[ed.x * 16 + lane]);
        ax = fmaf(nf, v.x, ax); ay = fmaf(nf, v.y, ay);
        az = fmaf(nf, v.z, az); aw = fmaf(nf, v.w, aw);
    }

    if (mode != 2) {
        xNew[o] = make_float4(ax, ay, az, aw);
    } else {
        float4 a = x0[o];
        float4 b = x1[o];
        out[o] = make_float4((a.x + b.x + v0.x + ax) * 0.25f,
                             (a.y + b.y + v0.y + ay) * 0.25f,
                             (a.z + b.z + v0.z + az) * 0.25f,
                             (a.w + b.w + v0.w + aw) * 0.25f);
    }
}

// ---------------------------------------------------------------------------
extern "C" void kernel_launch(void* const* d_in, const int* in_sizes, int n_in,
                              void* d_out, int out_size) {
    // Bind inputs by unique element count (robust to metadata ordering).
    const float* emb = nullptr;   // 6,400,000 f32
    const float* ew = nullptr;    // 1,600,000 f32
    const void* idx = nullptr;    // 3,200,000 elems (int32 or int64, detected)
    for (int i = 0; i < n_in; i++) {
        if (in_sizes[i] == ND) emb = (const float*)d_in[i];
        else if (in_sizes[i] == EE) ew = (const float*)d_in[i];
        else if (in_sizes[i] == 2 * EE) idx = d_in[i];
    }
    if (!emb) emb = (const float*)d_in[0];
    if (!ew) ew = (const float*)d_in[1];
    if (!idx) idx = d_in[2];

    float4* out = (float4*)d_out;
    float4* xA;
    float4* xB;
    cudaGetSymbolAddress((void**)&xA, g_xA);
    cudaGetSymbolAddress((void**)&xB, g_xB);

    const int T = 256;
    const int gN = (NN + T - 1) / T;            // 391
    const int gE4 = (EE / 4 + T - 1) / T;       // 1563
    const int gE2 = (EE / 2 + T - 1) / T;       // 3125
    const int gL = NN / 16;                     // 6250 (exact)

    const float4* embv = (const float4*)emb;

    // Precompute: degrees, dinv, CSR
    k_init<<<gN, T>>>(idx);
    k_count<<<gE4, T>>>(idx);
    k_scan1<<<NB, T>>>();   // also computes dinv
    k_scan2<<<1, 512>>>();
    k_scan3<<<NB, T>>>();
    k_fill<<<gE2, T>>>(idx, ew);

    // Layer 1: x1 <- A @ x0
    k_layer<<<gL, T>>>(embv, xB, nullptr, nullptr, nullptr, 0);
    // Layer 2: x2 <- A @ x1
    k_layer<<<gL, T>>>(xB, xA, nullptr, nullptr, nullptr, 1);
    // Layer 3: out = (x0 + x1 + x2 + A @ x2) / 4
    k_layer<<<gL, T>>>(xA, nullptr, embv, xB, out, 2);
}

// round 6
// speedup vs baseline: 1.1404x; 1.1404x over previous
#include <cuda_runtime.h>
#include <cuda_fp16.h>
#include <cstdint>

// LightGCN propagation: N=100000, E=1600000, D=64, L=3.
// out = (x0 + x1 + x2 + x3)/4, x_{l+1} = A_norm @ x_l (with self loops).
//
// R6: layers are LTS-bound (random 256B-row gathers from L2). Halve the bytes:
// store intermediate embeddings as fp16 (fp32 accumulation in registers).
// Layer loop back to coalesced-edge-load + shfl broadcast (R5's per-edge
// broadcast LDGs hit the LDG->LDG structural floor of 4cyc and regressed).
// One warp per node (no trip-count divergence), lane owns a half2 column pair.

#define NN 100000
#define EE 1600000
#define DD 64
#define ND (NN * DD)       // 6,400,000 floats
#define ND4 (ND / 4)       // 1,600,000
#define ND2 (ND / 2)       // 3,200,000 half2
#define NB 391             // ceil(NN / 256)

// Scratch (allocation-free: __device__ globals)
__device__ int g_is32;
__device__ float g_deg[NN];      // source-occurrence degree (incl. self loop)
__device__ float g_dinv[NN];
__device__ int g_indeg[NN];      // destination in-degree (excl. self loop)
__device__ int g_part[NB];
__device__ int g_boff[NB];
__device__ int g_start[NN + 1];  // CSR row starts (by destination)
__device__ int g_cursor[NN];
__device__ uint2 g_csr[EE];      // packed (src, norm_bits), grouped by dst
__device__ __half2 g_h0[ND2];    // x0 (emb) in half
__device__ __half2 g_h1[ND2];    // x1
__device__ __half2 g_h2[ND2];    // x2

// ---------------------------------------------------------------------------
// Init: degrees + index-dtype detection (JAX w/o x64 demotes int64 -> int32;
// element count is identical either way, so sample values to disambiguate).
// ---------------------------------------------------------------------------
__global__ __launch_bounds__(256) void k_init(const void* __restrict__ idx) {
    int i = blockIdx.x * blockDim.x + threadIdx.x;
    if (i < NN) {
        g_deg[i] = 1.0f;   // self loop contributes 1 to every degree
        g_indeg[i] = 0;
    }
    if (i == 0) {
        const long long* p = (const long long*)idx;
        int is64 = 1;
        for (int k = 0; k < 256; k++) {
            long long v = p[k];
            if (v < 0 || v >= (long long)NN) { is64 = 0; break; }
        }
        g_is32 = !is64;
    }
}

// Convert emb (fp32) -> g_h0 (half), float4 -> 2x half2 per thread.
__global__ __launch_bounds__(256) void k_h0(const float4* __restrict__ emb4) {
    int i = blockIdx.x * blockDim.x + threadIdx.x;
    if (i >= ND4) return;
    float4 v = __ldg(&emb4[i]);
    __half2 a = __floats2half2_rn(v.x, v.y);
    __half2 b = __floats2half2_rn(v.z, v.w);
    uint2 p;
    p.x = *reinterpret_cast<unsigned*>(&a);
    p.y = *reinterpret_cast<unsigned*>(&b);
    reinterpret_cast<uint2*>(g_h0)[i] = p;
}

// 4 edges per thread, vectorized int4 loads on the int32 path.
__global__ __launch_bounds__(256) void k_count(const void* __restrict__ idx) {
    int t = blockIdx.x * blockDim.x + threadIdx.x;
    int e = t * 4;
    if (e >= EE) return;
    int s0, s1, s2, s3, d0, d1, d2, d3;
    if (g_is32) {
        const int4* p = (const int4*)idx;
        int4 s = __ldg(&p[t]);
        int4 d = __ldg(&p[EE / 4 + t]);
        s0 = s.x; s1 = s.y; s2 = s.z; s3 = s.w;
        d0 = d.x; d1 = d.y; d2 = d.z; d3 = d.w;
    } else {
        const long long* p = (const long long*)idx;
        s0 = (int)p[e];      s1 = (int)p[e + 1];
        s2 = (int)p[e + 2];  s3 = (int)p[e + 3];
        d0 = (int)p[EE + e];     d1 = (int)p[EE + e + 1];
        d2 = (int)p[EE + e + 2]; d3 = (int)p[EE + e + 3];
    }
    atomicAdd(&g_deg[s0], 1.0f); atomicAdd(&g_deg[s1], 1.0f);
    atomicAdd(&g_deg[s2], 1.0f); atomicAdd(&g_deg[s3], 1.0f);
    atomicAdd(&g_indeg[d0], 1);  atomicAdd(&g_indeg[d1], 1);
    atomicAdd(&g_indeg[d2], 1);  atomicAdd(&g_indeg[d3], 1);
}

// ---------------------------------------------------------------------------
// Scan of in-degrees -> CSR starts (3-kernel hierarchy). scan1 also computes
// dinv (both depend only on k_count).
// ---------------------------------------------------------------------------
__global__ __launch_bounds__(256) void k_scan1() {
    __shared__ int sh[256];
    int i = blockIdx.x * 256 + threadIdx.x;
    sh[threadIdx.x] = (i < NN) ? g_indeg[i] : 0;
    if (i < NN) {
        float d = g_deg[i];
        g_dinv[i] = (d > 0.0f) ? rsqrtf(d) : 0.0f;
    }
    __syncthreads();
    for (int s = 128; s > 0; s >>= 1) {
        if (threadIdx.x < s) sh[threadIdx.x] += sh[threadIdx.x + s];
        __syncthreads();
    }
    if (threadIdx.x == 0) g_part[blockIdx.x] = sh[0];
}

__global__ __launch_bounds__(512) void k_scan2() {
    __shared__ int sh[512];
    int t = threadIdx.x;
    sh[t] = (t < NB) ? g_part[t] : 0;
    __syncthreads();
    for (int off = 1; off < 512; off <<= 1) {
        int v = (t >= off) ? sh[t - off] : 0;
        __syncthreads();
        sh[t] += v;
        __syncthreads();
    }
    if (t < NB) g_boff[t] = (t == 0) ? 0 : sh[t - 1];
}

__global__ __launch_bounds__(256) void k_scan3() {
    __shared__ int sh[256];
    int i = blockIdx.x * 256 + threadIdx.x;
    int v = (i < NN) ? g_indeg[i] : 0;
    sh[threadIdx.x] = v;
    __syncthreads();
    for (int off = 1; off < 256; off <<= 1) {
        int t = (threadIdx.x >= off) ? sh[threadIdx.x - off] : 0;
        __syncthreads();
        sh[threadIdx.x] += t;
        __syncthreads();
    }
    if (i < NN) {
        int excl = g_boff[blockIdx.x] + sh[threadIdx.x] - v;
        g_start[i] = excl;
        g_cursor[i] = excl;
        if (i == NN - 1) g_start[NN] = excl + v;
    }
}

// Fill CSR: 2 edges per thread, vectorized loads on the int32 path.
__global__ __launch_bounds__(256) void k_fill(const void* __restrict__ idx,
                                              const float* __restrict__ w) {
    int t = blockIdx.x * blockDim.x + threadIdx.x;
    int e = t * 2;
    if (e >= EE) return;
    int s0, s1, d0, d1;
    if (g_is32) {
        const int2* p = (const int2*)idx;
        int2 s = __ldg(&p[t]);
        int2 d = __ldg(&p[EE / 2 + t]);
        s0 = s.x; s1 = s.y; d0 = d.x; d1 = d.y;
    } else {
        const long long* p = (const long long*)idx;
        s0 = (int)p[e]; s1 = (int)p[e + 1];
        d0 = (int)p[EE + e]; d1 = (int)p[EE + e + 1];
    }
    float2 wv = __ldg((const float2*)(w + e));
    float n0 = g_dinv[s0] * wv.x * g_dinv[d0];
    float n1 = g_dinv[s1] * wv.y * g_dinv[d1];
    int p0 = atomicAdd(&g_cursor[d0], 1);
    g_csr[p0] = make_uint2((unsigned)s0, __float_as_uint(n0));
    int p1 = atomicAdd(&g_cursor[d1], 1);
    g_csr[p1] = make_uint2((unsigned)s1, __float_as_uint(n1));
}

// ---------------------------------------------------------------------------
// Layer kernel: ONE WARP per node; lane owns one half2 (2 feature columns).
// Edge records loaded coalesced (32/warp) and broadcast via shfl. fp32 accum.
//   acc = dinv[n]^2 * xOld[n] + sum_{e in CSR[n]} norm[e] * xOld[src[e]]
// mode 0/1: xNew = half(acc)
// mode 2:   out = (emb + x1 + xOld + acc) * 0.25  in fp32 (xOld == x2)
// ---------------------------------------------------------------------------
__global__ __launch_bounds__(256) void k_layer(const __half2* __restrict__ xOld,
                                               __half2* __restrict__ xNew,
                                               const float2* __restrict__ emb2,
                                               const __half2* __restrict__ x1h,
                                               float2* __restrict__ out2,
                                               int mode) {
    int lane = threadIdx.x & 31;
    int node = blockIdx.x * 8 + (threadIdx.x >> 5);  // grid covers exactly NN

    int start = g_start[node];
    int end = g_start[node + 1];
    float s = g_dinv[node];
    s *= s;

    int o = node * 32 + lane;
    float2 v0 = __half22float2(xOld[o]);
    float ax = s * v0.x, ay = s * v0.y;

    for (int base = start; base < end; base += 32) {
        int e = base + lane;
        uint2 ed = (e < end) ? g_csr[e] : make_uint2(0u, 0u);
        int m = end - base;
        if (m > 32) m = 32;
        for (int j = 0; j < m; j++) {
            unsigned sj = __shfl_sync(0xFFFFFFFFu, ed.x, j);
            float nf = __uint_as_float(__shfl_sync(0xFFFFFFFFu, ed.y, j));
            float2 v = __half22float2(__ldg(&xOld[sj * 32 + lane]));
            ax = fmaf(nf, v.x, ax);
            ay = fmaf(nf, v.y, ay);
        }
    }

    if (mode != 2) {
        xNew[o] = __floats2half2_rn(ax, ay);
    } else {
        float2 a = __ldg(&emb2[o]);
        float2 b = __half22float2(__ldg(&x1h[o]));
        out2[o] = make_float2((a.x + b.x + v0.x + ax) * 0.25f,
                              (a.y + b.y + v0.y + ay) * 0.25f);
    }
}

// ---------------------------------------------------------------------------
extern "C" void kernel_launch(void* const* d_in, const int* in_sizes, int n_in,
                              void* d_out, int out_size) {
    // Bind inputs by unique element count (robust to metadata ordering).
    const float* emb = nullptr;   // 6,400,000 f32
    const float* ew = nullptr;    // 1,600,000 f32
    const void* idx = nullptr;    // 3,200,000 elems (int32 or int64, detected)
    for (int i = 0; i < n_in; i++) {
        if (in_sizes[i] == ND) emb = (const float*)d_in[i];
        else if (in_sizes[i] == EE) ew = (const float*)d_in[i];
        else if (in_sizes[i] == 2 * EE) idx = d_in[i];
    }
    if (!emb) emb = (const float*)d_in[0];
    if (!ew) ew = (const float*)d_in[1];
    if (!idx) idx = d_in[2];

    float2* out2 = (float2*)d_out;

    __half2* h0;
    __half2* h1;
    __half2* h2;
    cudaGetSymbolAddress((void**)&h0, g_h0);
    cudaGetSymbolAddress((void**)&h1, g_h1);
    cudaGetSymbolAddress((void**)&h2, g_h2);

    const int T = 256;
    const int gN = (NN + T - 1) / T;            // 391
    const int gE4 = (EE / 4 + T - 1) / T;       // 1563
    const int gE2 = (EE / 2 + T - 1) / T;       // 3125
    const int gC = (ND4 + T - 1) / T;           // 6250
    const int gL = NN / 8;                      // 12500 (exact, 8 warps/block)

    // Precompute: degrees, dinv, CSR, half copy of emb
    k_init<<<gN, T>>>(idx);
    k_count<<<gE4, T>>>(idx);
    k_h0<<<gC, T>>>((const float4*)emb);
    k_scan1<<<NB, T>>>();   // also computes dinv
    k_scan2<<<1, 512>>>();
    k_scan3<<<NB, T>>>();
    k_fill<<<gE2, T>>>(idx, ew);

    // Layer 1: x1 <- A @ x0
    k_layer<<<gL, T>>>(h0, h1, nullptr, nullptr, nullptr, 0);
    // Layer 2: x2 <- A @ x1
    k_layer<<<gL, T>>>(h1, h2, nullptr, nullptr, nullptr, 1);
    // Layer 3: out = (x0 + x1 + x2 + A @ x2) / 4   (fp32 out)
    k_layer<<<gL, T>>>(h2, nullptr, (const float2*)emb, h1, out2, 2);
}